// round 9
// baseline (speedup 1.0000x reference)
#include <cuda_runtime.h>
#include <cuda_bf16.h>
#include <cstdint>
#include <cstddef>

// Stereo cost volume via warp-level bf16 MMA band-GEMM:
//   out[bh, w, d] = sum_c ref[bh, w + 63 - d, c] * aux[bh, w, c]
// Per (bh, 128-w tile): C[i, j] = sum_c aux[w0+i, c] * ref[w0+j, c]
// computed with mma.sync.m16n8k16 (bf16 hi/lo split, 3 passes, fp32 acc),
// band-restricted per 32-row m-block to a 96-col ref window; epilogue
// scatters the diagonal band out[i, d] = C[i, i+63-d].

namespace {

constexpr int kW  = 384;
constexpr int kC  = 128;
constexpr int kD  = 64;
constexpr int kRW = 447;

constexpr int WTILE = 128;
constexpr int NREF  = 191;
constexpr int BROWS = 192;
constexpr int NTHREADS = 256;

// Dynamic smem layout (per 64-channel chunk): rows of 64 bf16 = 128 B, SW128.
constexpr int OFF_AH = 0;                 // aux hi: 128 rows
constexpr int OFF_AL = OFF_AH + 128*128;  // aux lo
constexpr int OFF_BH = OFF_AL + 128*128;  // ref hi: 192 rows
constexpr int OFF_BL = OFF_BH + 192*128;  // ref lo
constexpr int SMEM_TOTAL = OFF_BL + 192*128;  // 81920 B

__device__ __forceinline__ uint32_t smem_u32(const void* p) {
    uint32_t a;
    asm("{ .reg .u64 t; cvta.to.shared.u64 t, %1; cvt.u32.u64 %0, t; }"
        : "=r"(a) : "l"(p));
    return a;
}

__device__ __forceinline__ void ldsm_x4(uint32_t (&r)[4], uint32_t addr) {
    asm volatile("ldmatrix.sync.aligned.m8n8.x4.shared.b16 {%0,%1,%2,%3}, [%4];"
                 : "=r"(r[0]), "=r"(r[1]), "=r"(r[2]), "=r"(r[3]) : "r"(addr));
}

__device__ __forceinline__ void mma16816(float* c, const uint32_t* a,
                                         uint32_t b0, uint32_t b1) {
    asm volatile(
        "mma.sync.aligned.m16n8k16.row.col.f32.bf16.bf16.f32 "
        "{%0,%1,%2,%3}, {%4,%5,%6,%7}, {%8,%9}, {%0,%1,%2,%3};"
        : "+f"(c[0]), "+f"(c[1]), "+f"(c[2]), "+f"(c[3])
        : "r"(a[0]), "r"(a[1]), "r"(a[2]), "r"(a[3]), "r"(b0), "r"(b1));
}

__global__ __launch_bounds__(NTHREADS, 2)
void cost_volume_mma_kernel(const float* __restrict__ ref,
                            const float* __restrict__ aux,
                            float* __restrict__ out) {
    extern __shared__ char smem[];
    const uint32_t sb = smem_u32(smem);
    const int tid  = threadIdx.x;
    const int lane = tid & 31;
    const int wid  = tid >> 5;
    const int bh    = blockIdx.y;
    const int wbase = blockIdx.x * WTILE;

    const float* refg = ref + ((size_t)bh * kRW + wbase) * kC;
    const float* auxg = aux + ((size_t)bh * kW  + wbase) * kC;

    const int mq = wid >> 1;              // m-block 0..3 -> rows 32*mq
    const int nh = wid & 1;               // n-half of the 96-col window
    const int i0 = 32 * mq;
    const int jbase = 32 * mq + 48 * nh;  // ref-col window base for this warp

    // acc[mf][fn][4]: mf = m16 frag (rows i0+16*mf..+15), fn = n8 frag
    float acc[2][6][4];
    #pragma unroll
    for (int a = 0; a < 2; ++a)
        #pragma unroll
        for (int b = 0; b < 6; ++b)
            #pragma unroll
            for (int c = 0; c < 4; ++c)
                acc[a][b][c] = 0.0f;

    // Per-lane ldmatrix addressing (k-contiguous rows, SW128 swizzle).
    // Address of (row, k-byte ko) = (row<<7) + (ko ^ ((row&7)<<4)).
    // NOTE: ko must be XORed into the swizzled column bits, not added.
    const int a_row = i0 + (lane & 15);
    const int b_row = jbase + (lane & 15);
    const int khalf = lane >> 4;
    const unsigned a_rb = (unsigned)a_row << 7;
    const unsigned b_rb = (unsigned)b_row << 7;
    const unsigned a_sw = ((unsigned)a_row & 7) << 4;
    const unsigned b_sw = ((unsigned)b_row & 7) << 4;

    for (int chunk = 0; chunk < 2; ++chunk) {
        const int cb = chunk * 64;

        // ---- stage: LDG float4 -> bf16 hi/lo split -> swizzled STS ----
        #pragma unroll 4
        for (int it = 0; it < 20; ++it) {
            int id = tid + it * NTHREADS;   // 3072 ref + 2048 aux 8B-stores
            const float* src;
            int dsth, dstl;
            if (id < BROWS * 16) {
                int r = id >> 4, fq = id & 15;
                int rr = (r < NREF) ? r : (NREF - 1);   // pad row 191
                src = refg + (size_t)rr * kC + cb + fq * 4;
                unsigned off = ((unsigned)r << 7) | ((unsigned)fq << 3);
                unsigned sw = off ^ (((unsigned)r & 7) << 4);
                dsth = OFF_BH + sw; dstl = OFF_BL + sw;
            } else {
                int id2 = id - BROWS * 16;
                int w = id2 >> 4, fq = id2 & 15;
                src = auxg + (size_t)w * kC + cb + fq * 4;
                unsigned off = ((unsigned)w << 7) | ((unsigned)fq << 3);
                unsigned sw = off ^ (((unsigned)w & 7) << 4);
                dsth = OFF_AH + sw; dstl = OFF_AL + sw;
            }
            float4 x = *reinterpret_cast<const float4*>(src);
            __nv_bfloat162 h01 = __floats2bfloat162_rn(x.x, x.y);
            __nv_bfloat162 h23 = __floats2bfloat162_rn(x.z, x.w);
            float l0 = x.x - __bfloat162float(h01.x);
            float l1 = x.y - __bfloat162float(h01.y);
            float l2 = x.z - __bfloat162float(h23.x);
            float l3 = x.w - __bfloat162float(h23.y);
            __nv_bfloat162 q01 = __floats2bfloat162_rn(l0, l1);
            __nv_bfloat162 q23 = __floats2bfloat162_rn(l2, l3);
            *reinterpret_cast<uint2*>(smem + dsth) =
                make_uint2(reinterpret_cast<unsigned&>(h01),
                           reinterpret_cast<unsigned&>(h23));
            *reinterpret_cast<uint2*>(smem + dstl) =
                make_uint2(reinterpret_cast<unsigned&>(q01),
                           reinterpret_cast<unsigned&>(q23));
        }
        __syncthreads();

        // ---- compute: 4 k-steps of 16 channels; 3 passes per k-step ----
        #pragma unroll
        for (int ks = 0; ks < 4; ++ks) {
            const unsigned ko = (unsigned)(2 * ks + khalf) << 4;
            const unsigned a_off = a_rb + (ko ^ a_sw);
            const unsigned b_off = b_rb + (ko ^ b_sw);
            uint32_t Ah0[4], Ah1[4], Al0[4], Al1[4];
            uint32_t Bh[3][4], Bl[3][4];

            ldsm_x4(Ah0, sb + OFF_AH + a_off);
            ldsm_x4(Ah1, sb + OFF_AH + a_off + 16 * 128);
            #pragma unroll
            for (int g = 0; g < 3; ++g)
                ldsm_x4(Bh[g], sb + OFF_BH + b_off + g * (16 * 128));

            // pass hh: Ah x Bh
            #pragma unroll
            for (int fn = 0; fn < 6; ++fn) {
                uint32_t b0 = Bh[fn >> 1][fn & 1];
                uint32_t b1 = Bh[fn >> 1][(fn & 1) + 2];
                mma16816(acc[0][fn], Ah0, b0, b1);
                mma16816(acc[1][fn], Ah1, b0, b1);
            }

            // pass hl: Ah x Bl
            #pragma unroll
            for (int g = 0; g < 3; ++g)
                ldsm_x4(Bl[g], sb + OFF_BL + b_off + g * (16 * 128));
            #pragma unroll
            for (int fn = 0; fn < 6; ++fn) {
                uint32_t b0 = Bl[fn >> 1][fn & 1];
                uint32_t b1 = Bl[fn >> 1][(fn & 1) + 2];
                mma16816(acc[0][fn], Ah0, b0, b1);
                mma16816(acc[1][fn], Ah1, b0, b1);
            }

            // pass lh: Al x Bh
            ldsm_x4(Al0, sb + OFF_AL + a_off);
            ldsm_x4(Al1, sb + OFF_AL + a_off + 16 * 128);
            #pragma unroll
            for (int fn = 0; fn < 6; ++fn) {
                uint32_t b0 = Bh[fn >> 1][fn & 1];
                uint32_t b1 = Bh[fn >> 1][(fn & 1) + 2];
                mma16816(acc[0][fn], Al0, b0, b1);
                mma16816(acc[1][fn], Al1, b0, b1);
            }
        }
        __syncthreads();
    }

    // ---- epilogue: band scatter out[i, i+63-j] = C[i, j] ----
    #pragma unroll
    for (int mf = 0; mf < 2; ++mf) {
        #pragma unroll
        for (int rr = 0; rr < 2; ++rr) {
            const int rA = i0 + 16 * mf + (lane >> 2) + 8 * rr;
            float* orow = out + ((size_t)(bh * kW + wbase + rA)) * kD;
            #pragma unroll
            for (int fn = 0; fn < 6; ++fn) {
                #pragma unroll
                for (int cc = 0; cc < 2; ++cc) {
                    int j = jbase + 8 * fn + 2 * (lane & 3) + cc;
                    int d = rA + 63 - j;
                    if (d >= 0 && d < kD)
                        orow[d] = acc[mf][fn][2 * rr + cc];
                }
            }
        }
    }
}

}  // namespace

extern "C" void kernel_launch(void* const* d_in, const int* in_sizes, int n_in,
                              void* d_out, int out_size) {
    const float* ref = (const float*)d_in[0];  // [1536, 447, 128] f32
    const float* aux = (const float*)d_in[1];  // [1536, 384, 128] f32
    float* out = (float*)d_out;                // [1536, 384, 64]  f32
    (void)in_sizes; (void)n_in; (void)out_size;

    cudaFuncSetAttribute(cost_volume_mma_kernel,
                         cudaFuncAttributeMaxDynamicSharedMemorySize, SMEM_TOTAL);
    dim3 grid(kW / WTILE, 1536);  // (3, 1536)
    cost_volume_mma_kernel<<<grid, NTHREADS, SMEM_TOTAL>>>(ref, aux, out);
}

// round 10
// speedup vs baseline: 1.0175x; 1.0175x over previous
#include <cuda_runtime.h>
#include <cuda_bf16.h>
#include <cstdint>
#include <cstddef>

// Stereo cost volume via warp-level bf16 MMA band-GEMM:
//   out[bh, w, d] = sum_c ref[bh, w + 63 - d, c] * aux[bh, w, c]
// Per (bh, 128-w tile): C[i, j] = sum_c aux[w0+i, c] * ref[w0+j, c]
// computed with mma.sync.m16n8k16 (bf16 hi/lo split, 3 passes, fp32 acc),
// band-restricted per 32-row m-block to a 96-col ref window; epilogue
// scatters the diagonal band out[i, d] = C[i, i+63-d].

namespace {

constexpr int kW  = 384;
constexpr int kC  = 128;
constexpr int kD  = 64;
constexpr int kRW = 447;

constexpr int WTILE = 128;
constexpr int NREF  = 191;
constexpr int BROWS = 192;
constexpr int NTHREADS = 256;

// Dynamic smem layout (per 64-channel chunk): rows of 64 bf16 = 128 B, SW128.
constexpr int OFF_AH = 0;                 // aux hi: 128 rows
constexpr int OFF_AL = OFF_AH + 128*128;  // aux lo
constexpr int OFF_BH = OFF_AL + 128*128;  // ref hi: 192 rows
constexpr int OFF_BL = OFF_BH + 192*128;  // ref lo
constexpr int SMEM_TOTAL = OFF_BL + 192*128;  // 81920 B

__device__ __forceinline__ uint32_t smem_u32(const void* p) {
    uint32_t a;
    asm("{ .reg .u64 t; cvta.to.shared.u64 t, %1; cvt.u32.u64 %0, t; }"
        : "=r"(a) : "l"(p));
    return a;
}

__device__ __forceinline__ void ldsm_x4(uint32_t (&r)[4], uint32_t addr) {
    asm volatile("ldmatrix.sync.aligned.m8n8.x4.shared.b16 {%0,%1,%2,%3}, [%4];"
                 : "=r"(r[0]), "=r"(r[1]), "=r"(r[2]), "=r"(r[3]) : "r"(addr));
}

__device__ __forceinline__ void mma16816(float* c, const uint32_t* a,
                                         uint32_t b0, uint32_t b1) {
    asm volatile(
        "mma.sync.aligned.m16n8k16.row.col.f32.bf16.bf16.f32 "
        "{%0,%1,%2,%3}, {%4,%5,%6,%7}, {%8,%9}, {%0,%1,%2,%3};"
        : "+f"(c[0]), "+f"(c[1]), "+f"(c[2]), "+f"(c[3])
        : "r"(a[0]), "r"(a[1]), "r"(a[2]), "r"(a[3]), "r"(b0), "r"(b1));
}

__global__ __launch_bounds__(NTHREADS, 2)
void cost_volume_mma_kernel(const float* __restrict__ ref,
                            const float* __restrict__ aux,
                            float* __restrict__ out) {
    extern __shared__ char smem[];
    const uint32_t sb = smem_u32(smem);
    const int tid  = threadIdx.x;
    const int lane = tid & 31;
    const int wid  = tid >> 5;
    const int bh    = blockIdx.y;
    const int wbase = blockIdx.x * WTILE;

    const float* refg = ref + ((size_t)bh * kRW + wbase) * kC;
    const float* auxg = aux + ((size_t)bh * kW  + wbase) * kC;

    const int mq = wid >> 1;              // m-block 0..3 -> rows 32*mq
    const int nh = wid & 1;               // n-half of the 96-col window
    const int i0 = 32 * mq;
    const int jbase = 32 * mq + 48 * nh;  // ref-col window base for this warp

    // acc[mf][fn][4]: mf = m16 frag (rows i0+16*mf..+15), fn = n8 frag
    float acc[2][6][4];
    #pragma unroll
    for (int a = 0; a < 2; ++a)
        #pragma unroll
        for (int b = 0; b < 6; ++b)
            #pragma unroll
            for (int c = 0; c < 4; ++c)
                acc[a][b][c] = 0.0f;

    // Per-lane ldmatrix addressing (k-contiguous rows, SW128 swizzle).
    // Address of (row, k-byte ko) = (row<<7) + (ko ^ ((row&7)<<4)).
    // NOTE: ko must be XORed into the swizzled column bits, not added.
    const int a_row = i0 + (lane & 15);
    const int b_row = jbase + (lane & 15);
    const int khalf = lane >> 4;
    const unsigned a_rb = (unsigned)a_row << 7;
    const unsigned b_rb = (unsigned)b_row << 7;
    const unsigned a_sw = ((unsigned)a_row & 7) << 4;
    const unsigned b_sw = ((unsigned)b_row & 7) << 4;

    for (int chunk = 0; chunk < 2; ++chunk) {
        const int cb = chunk * 64;

        // ---- stage: LDG float4 -> bf16 hi/lo split -> swizzled STS ----
        #pragma unroll 4
        for (int it = 0; it < 20; ++it) {
            int id = tid + it * NTHREADS;   // 3072 ref + 2048 aux 8B-stores
            const float* src;
            int dsth, dstl;
            if (id < BROWS * 16) {
                int r = id >> 4, fq = id & 15;
                int rr = (r < NREF) ? r : (NREF - 1);   // pad row 191
                src = refg + (size_t)rr * kC + cb + fq * 4;
                unsigned off = ((unsigned)r << 7) | ((unsigned)fq << 3);
                unsigned sw = off ^ (((unsigned)r & 7) << 4);
                dsth = OFF_BH + sw; dstl = OFF_BL + sw;
            } else {
                int id2 = id - BROWS * 16;
                int w = id2 >> 4, fq = id2 & 15;
                src = auxg + (size_t)w * kC + cb + fq * 4;
                unsigned off = ((unsigned)w << 7) | ((unsigned)fq << 3);
                unsigned sw = off ^ (((unsigned)w & 7) << 4);
                dsth = OFF_AH + sw; dstl = OFF_AL + sw;
            }
            float4 x = *reinterpret_cast<const float4*>(src);
            __nv_bfloat162 h01 = __floats2bfloat162_rn(x.x, x.y);
            __nv_bfloat162 h23 = __floats2bfloat162_rn(x.z, x.w);
            float l0 = x.x - __bfloat162float(h01.x);
            float l1 = x.y - __bfloat162float(h01.y);
            float l2 = x.z - __bfloat162float(h23.x);
            float l3 = x.w - __bfloat162float(h23.y);
            __nv_bfloat162 q01 = __floats2bfloat162_rn(l0, l1);
            __nv_bfloat162 q23 = __floats2bfloat162_rn(l2, l3);
            *reinterpret_cast<uint2*>(smem + dsth) =
                make_uint2(reinterpret_cast<unsigned&>(h01),
                           reinterpret_cast<unsigned&>(h23));
            *reinterpret_cast<uint2*>(smem + dstl) =
                make_uint2(reinterpret_cast<unsigned&>(q01),
                           reinterpret_cast<unsigned&>(q23));
        }
        __syncthreads();

        // ---- compute: 4 k-steps of 16 channels; 3 passes per k-step ----
        #pragma unroll
        for (int ks = 0; ks < 4; ++ks) {
            const unsigned ko = (unsigned)(2 * ks + khalf) << 4;
            const unsigned a_off = a_rb + (ko ^ a_sw);
            const unsigned b_off = b_rb + (ko ^ b_sw);
            uint32_t Ah0[4], Ah1[4], Al0[4], Al1[4];
            uint32_t Bh[3][4], Bl[3][4];

            ldsm_x4(Ah0, sb + OFF_AH + a_off);
            ldsm_x4(Ah1, sb + OFF_AH + a_off + 16 * 128);
            #pragma unroll
            for (int g = 0; g < 3; ++g)
                ldsm_x4(Bh[g], sb + OFF_BH + b_off + g * (16 * 128));

            // pass hh: Ah x Bh
            #pragma unroll
            for (int fn = 0; fn < 6; ++fn) {
                uint32_t b0 = Bh[fn >> 1][fn & 1];
                uint32_t b1 = Bh[fn >> 1][(fn & 1) + 2];
                mma16816(acc[0][fn], Ah0, b0, b1);
                mma16816(acc[1][fn], Ah1, b0, b1);
            }

            // pass hl: Ah x Bl
            #pragma unroll
            for (int g = 0; g < 3; ++g)
                ldsm_x4(Bl[g], sb + OFF_BL + b_off + g * (16 * 128));
            #pragma unroll
            for (int fn = 0; fn < 6; ++fn) {
                uint32_t b0 = Bl[fn >> 1][fn & 1];
                uint32_t b1 = Bl[fn >> 1][(fn & 1) + 2];
                mma16816(acc[0][fn], Ah0, b0, b1);
                mma16816(acc[1][fn], Ah1, b0, b1);
            }

            // pass lh: Al x Bh
            ldsm_x4(Al0, sb + OFF_AL + a_off);
            ldsm_x4(Al1, sb + OFF_AL + a_off + 16 * 128);
            #pragma unroll
            for (int fn = 0; fn < 6; ++fn) {
                uint32_t b0 = Bh[fn >> 1][fn & 1];
                uint32_t b1 = Bh[fn >> 1][(fn & 1) + 2];
                mma16816(acc[0][fn], Al0, b0, b1);
                mma16816(acc[1][fn], Al1, b0, b1);
            }
        }
        __syncthreads();
    }

    // ---- epilogue: band scatter out[i, i+63-j] = C[i, j] ----
    #pragma unroll
    for (int mf = 0; mf < 2; ++mf) {
        #pragma unroll
        for (int rr = 0; rr < 2; ++rr) {
            const int rA = i0 + 16 * mf + (lane >> 2) + 8 * rr;
            float* orow = out + ((size_t)(bh * kW + wbase + rA)) * kD;
            #pragma unroll
            for (int fn = 0; fn < 6; ++fn) {
                #pragma unroll
                for (int cc = 0; cc < 2; ++cc) {
                    int j = jbase + 8 * fn + 2 * (lane & 3) + cc;
                    int d = rA + 63 - j;
                    if (d >= 0 && d < kD)
                        orow[d] = acc[mf][fn][2 * rr + cc];
                }
            }
        }
    }
}

}  // namespace

extern "C" void kernel_launch(void* const* d_in, const int* in_sizes, int n_in,
                              void* d_out, int out_size) {
    const float* ref = (const float*)d_in[0];  // [1536, 447, 128] f32
    const float* aux = (const float*)d_in[1];  // [1536, 384, 128] f32
    float* out = (float*)d_out;                // [1536, 384, 64]  f32
    (void)in_sizes; (void)n_in; (void)out_size;

    cudaFuncSetAttribute(cost_volume_mma_kernel,
                         cudaFuncAttributeMaxDynamicSharedMemorySize, SMEM_TOTAL);
    dim3 grid(kW / WTILE, 1536);  // (3, 1536)
    cost_volume_mma_kernel<<<grid, NTHREADS, SMEM_TOTAL>>>(ref, aux, out);
}

// round 11
// speedup vs baseline: 1.0181x; 1.0006x over previous
#include <cuda_runtime.h>
#include <cuda_bf16.h>
#include <cstdint>
#include <cstddef>

// Stereo cost volume via warp-level bf16 MMA band-GEMM:
//   out[bh, w, d] = sum_c ref[bh, w + 63 - d, c] * aux[bh, w, c]
// Per (bh, 128-w tile): C[i, j] = sum_c aux[w0+i, c] * ref[w0+j, c]
// computed with mma.sync.m16n8k16 (bf16 hi/lo split, 3 passes, fp32 acc),
// band-restricted per 32-row m-block to a 96-col ref window; epilogue
// scatters the diagonal band out[i, d] = C[i, i+63-d].

namespace {

constexpr int kW  = 384;
constexpr int kC  = 128;
constexpr int kD  = 64;
constexpr int kRW = 447;

constexpr int WTILE = 128;
constexpr int NREF  = 191;
constexpr int BROWS = 192;
constexpr int NTHREADS = 256;

// Dynamic smem layout (per 64-channel chunk): rows of 64 bf16 = 128 B, SW128.
constexpr int OFF_AH = 0;                 // aux hi: 128 rows
constexpr int OFF_AL = OFF_AH + 128*128;  // aux lo
constexpr int OFF_BH = OFF_AL + 128*128;  // ref hi: 192 rows
constexpr int OFF_BL = OFF_BH + 192*128;  // ref lo
constexpr int SMEM_TOTAL = OFF_BL + 192*128;  // 81920 B

__device__ __forceinline__ uint32_t smem_u32(const void* p) {
    uint32_t a;
    asm("{ .reg .u64 t; cvta.to.shared.u64 t, %1; cvt.u32.u64 %0, t; }"
        : "=r"(a) : "l"(p));
    return a;
}

__device__ __forceinline__ void ldsm_x4(uint32_t (&r)[4], uint32_t addr) {
    asm volatile("ldmatrix.sync.aligned.m8n8.x4.shared.b16 {%0,%1,%2,%3}, [%4];"
                 : "=r"(r[0]), "=r"(r[1]), "=r"(r[2]), "=r"(r[3]) : "r"(addr));
}

__device__ __forceinline__ void mma16816(float* c, const uint32_t* a,
                                         uint32_t b0, uint32_t b1) {
    asm volatile(
        "mma.sync.aligned.m16n8k16.row.col.f32.bf16.bf16.f32 "
        "{%0,%1,%2,%3}, {%4,%5,%6,%7}, {%8,%9}, {%0,%1,%2,%3};"
        : "+f"(c[0]), "+f"(c[1]), "+f"(c[2]), "+f"(c[3])
        : "r"(a[0]), "r"(a[1]), "r"(a[2]), "r"(a[3]), "r"(b0), "r"(b1));
}

__global__ __launch_bounds__(NTHREADS, 2)
void cost_volume_mma_kernel(const float* __restrict__ ref,
                            const float* __restrict__ aux,
                            float* __restrict__ out) {
    extern __shared__ char smem[];
    const uint32_t sb = smem_u32(smem);
    const int tid  = threadIdx.x;
    const int lane = tid & 31;
    const int wid  = tid >> 5;
    const int bh    = blockIdx.y;
    const int wbase = blockIdx.x * WTILE;

    const float* refg = ref + ((size_t)bh * kRW + wbase) * kC;
    const float* auxg = aux + ((size_t)bh * kW  + wbase) * kC;

    const int mq = wid >> 1;              // m-block 0..3 -> rows 32*mq
    const int nh = wid & 1;               // n-half of the 96-col window
    const int i0 = 32 * mq;
    const int jbase = 32 * mq + 48 * nh;  // ref-col window base for this warp

    // acc[mf][fn][4]: mf = m16 frag (rows i0+16*mf..+15), fn = n8 frag
    float acc[2][6][4];
    #pragma unroll
    for (int a = 0; a < 2; ++a)
        #pragma unroll
        for (int b = 0; b < 6; ++b)
            #pragma unroll
            for (int c = 0; c < 4; ++c)
                acc[a][b][c] = 0.0f;

    // Per-lane ldmatrix addressing (k-contiguous rows, SW128 swizzle).
    // Address of (row, k-byte ko) = (row<<7) + (ko ^ ((row&7)<<4)).
    // NOTE: ko must be XORed into the swizzled column bits, not added.
    const int a_row = i0 + (lane & 15);
    const int b_row = jbase + (lane & 15);
    const int khalf = lane >> 4;
    const unsigned a_rb = (unsigned)a_row << 7;
    const unsigned b_rb = (unsigned)b_row << 7;
    const unsigned a_sw = ((unsigned)a_row & 7) << 4;
    const unsigned b_sw = ((unsigned)b_row & 7) << 4;

    for (int chunk = 0; chunk < 2; ++chunk) {
        const int cb = chunk * 64;

        // ---- stage: LDG float4 -> bf16 hi/lo split -> swizzled STS ----
        #pragma unroll 4
        for (int it = 0; it < 20; ++it) {
            int id = tid + it * NTHREADS;   // 3072 ref + 2048 aux 8B-stores
            const float* src;
            int dsth, dstl;
            if (id < BROWS * 16) {
                int r = id >> 4, fq = id & 15;
                int rr = (r < NREF) ? r : (NREF - 1);   // pad row 191
                src = refg + (size_t)rr * kC + cb + fq * 4;
                unsigned off = ((unsigned)r << 7) | ((unsigned)fq << 3);
                unsigned sw = off ^ (((unsigned)r & 7) << 4);
                dsth = OFF_BH + sw; dstl = OFF_BL + sw;
            } else {
                int id2 = id - BROWS * 16;
                int w = id2 >> 4, fq = id2 & 15;
                src = auxg + (size_t)w * kC + cb + fq * 4;
                unsigned off = ((unsigned)w << 7) | ((unsigned)fq << 3);
                unsigned sw = off ^ (((unsigned)w & 7) << 4);
                dsth = OFF_AH + sw; dstl = OFF_AL + sw;
            }
            float4 x = *reinterpret_cast<const float4*>(src);
            __nv_bfloat162 h01 = __floats2bfloat162_rn(x.x, x.y);
            __nv_bfloat162 h23 = __floats2bfloat162_rn(x.z, x.w);
            float l0 = x.x - __bfloat162float(h01.x);
            float l1 = x.y - __bfloat162float(h01.y);
            float l2 = x.z - __bfloat162float(h23.x);
            float l3 = x.w - __bfloat162float(h23.y);
            __nv_bfloat162 q01 = __floats2bfloat162_rn(l0, l1);
            __nv_bfloat162 q23 = __floats2bfloat162_rn(l2, l3);
            *reinterpret_cast<uint2*>(smem + dsth) =
                make_uint2(reinterpret_cast<unsigned&>(h01),
                           reinterpret_cast<unsigned&>(h23));
            *reinterpret_cast<uint2*>(smem + dstl) =
                make_uint2(reinterpret_cast<unsigned&>(q01),
                           reinterpret_cast<unsigned&>(q23));
        }
        __syncthreads();

        // ---- compute: 4 k-steps of 16 channels; 3 passes per k-step ----
        #pragma unroll
        for (int ks = 0; ks < 4; ++ks) {
            const unsigned ko = (unsigned)(2 * ks + khalf) << 4;
            const unsigned a_off = a_rb + (ko ^ a_sw);
            const unsigned b_off = b_rb + (ko ^ b_sw);
            uint32_t Ah0[4], Ah1[4], Al0[4], Al1[4];
            uint32_t Bh[3][4], Bl[3][4];

            ldsm_x4(Ah0, sb + OFF_AH + a_off);
            ldsm_x4(Ah1, sb + OFF_AH + a_off + 16 * 128);
            #pragma unroll
            for (int g = 0; g < 3; ++g)
                ldsm_x4(Bh[g], sb + OFF_BH + b_off + g * (16 * 128));

            // pass hh: Ah x Bh
            #pragma unroll
            for (int fn = 0; fn < 6; ++fn) {
                uint32_t b0 = Bh[fn >> 1][fn & 1];
                uint32_t b1 = Bh[fn >> 1][(fn & 1) + 2];
                mma16816(acc[0][fn], Ah0, b0, b1);
                mma16816(acc[1][fn], Ah1, b0, b1);
            }

            // pass hl: Ah x Bl
            #pragma unroll
            for (int g = 0; g < 3; ++g)
                ldsm_x4(Bl[g], sb + OFF_BL + b_off + g * (16 * 128));
            #pragma unroll
            for (int fn = 0; fn < 6; ++fn) {
                uint32_t b0 = Bl[fn >> 1][fn & 1];
                uint32_t b1 = Bl[fn >> 1][(fn & 1) + 2];
                mma16816(acc[0][fn], Ah0, b0, b1);
                mma16816(acc[1][fn], Ah1, b0, b1);
            }

            // pass lh: Al x Bh
            ldsm_x4(Al0, sb + OFF_AL + a_off);
            ldsm_x4(Al1, sb + OFF_AL + a_off + 16 * 128);
            #pragma unroll
            for (int fn = 0; fn < 6; ++fn) {
                uint32_t b0 = Bh[fn >> 1][fn & 1];
                uint32_t b1 = Bh[fn >> 1][(fn & 1) + 2];
                mma16816(acc[0][fn], Al0, b0, b1);
                mma16816(acc[1][fn], Al1, b0, b1);
            }
        }
        __syncthreads();
    }

    // ---- epilogue: band scatter out[i, i+63-j] = C[i, j] ----
    #pragma unroll
    for (int mf = 0; mf < 2; ++mf) {
        #pragma unroll
        for (int rr = 0; rr < 2; ++rr) {
            const int rA = i0 + 16 * mf + (lane >> 2) + 8 * rr;
            float* orow = out + ((size_t)(bh * kW + wbase + rA)) * kD;
            #pragma unroll
            for (int fn = 0; fn < 6; ++fn) {
                #pragma unroll
                for (int cc = 0; cc < 2; ++cc) {
                    int j = jbase + 8 * fn + 2 * (lane & 3) + cc;
                    int d = rA + 63 - j;
                    if (d >= 0 && d < kD)
                        orow[d] = acc[mf][fn][2 * rr + cc];
                }
            }
        }
    }
}

}  // namespace

extern "C" void kernel_launch(void* const* d_in, const int* in_sizes, int n_in,
                              void* d_out, int out_size) {
    const float* ref = (const float*)d_in[0];  // [1536, 447, 128] f32
    const float* aux = (const float*)d_in[1];  // [1536, 384, 128] f32
    float* out = (float*)d_out;                // [1536, 384, 64]  f32
    (void)in_sizes; (void)n_in; (void)out_size;

    cudaFuncSetAttribute(cost_volume_mma_kernel,
                         cudaFuncAttributeMaxDynamicSharedMemorySize, SMEM_TOTAL);
    dim3 grid(kW / WTILE, 1536);  // (3, 1536)
    cost_volume_mma_kernel<<<grid, NTHREADS, SMEM_TOTAL>>>(ref, aux, out);
}

// round 12
// speedup vs baseline: 1.0198x; 1.0016x over previous
#include <cuda_runtime.h>
#include <cuda_bf16.h>
#include <cstdint>
#include <cstddef>

// Stereo cost volume via warp-level bf16 MMA band-GEMM:
//   out[bh, w, d] = sum_c ref[bh, w + 63 - d, c] * aux[bh, w, c]
// Per (bh, 128-w tile): C[i, j] = sum_c aux[w0+i, c] * ref[w0+j, c]
// computed with mma.sync.m16n8k16 (bf16 hi/lo split, 3 passes, fp32 acc),
// band-restricted per 32-row m-block to a 96-col ref window; epilogue
// scatters the diagonal band out[i, d] = C[i, i+63-d].

namespace {

constexpr int kW  = 384;
constexpr int kC  = 128;
constexpr int kD  = 64;
constexpr int kRW = 447;

constexpr int WTILE = 128;
constexpr int NREF  = 191;
constexpr int BROWS = 192;
constexpr int NTHREADS = 256;

// Dynamic smem layout (per 64-channel chunk): rows of 64 bf16 = 128 B, SW128.
constexpr int OFF_AH = 0;                 // aux hi: 128 rows
constexpr int OFF_AL = OFF_AH + 128*128;  // aux lo
constexpr int OFF_BH = OFF_AL + 128*128;  // ref hi: 192 rows
constexpr int OFF_BL = OFF_BH + 192*128;  // ref lo
constexpr int SMEM_TOTAL = OFF_BL + 192*128;  // 81920 B

__device__ __forceinline__ uint32_t smem_u32(const void* p) {
    uint32_t a;
    asm("{ .reg .u64 t; cvta.to.shared.u64 t, %1; cvt.u32.u64 %0, t; }"
        : "=r"(a) : "l"(p));
    return a;
}

__device__ __forceinline__ void ldsm_x4(uint32_t (&r)[4], uint32_t addr) {
    asm volatile("ldmatrix.sync.aligned.m8n8.x4.shared.b16 {%0,%1,%2,%3}, [%4];"
                 : "=r"(r[0]), "=r"(r[1]), "=r"(r[2]), "=r"(r[3]) : "r"(addr));
}

__device__ __forceinline__ void mma16816(float* c, const uint32_t* a,
                                         uint32_t b0, uint32_t b1) {
    asm volatile(
        "mma.sync.aligned.m16n8k16.row.col.f32.bf16.bf16.f32 "
        "{%0,%1,%2,%3}, {%4,%5,%6,%7}, {%8,%9}, {%0,%1,%2,%3};"
        : "+f"(c[0]), "+f"(c[1]), "+f"(c[2]), "+f"(c[3])
        : "r"(a[0]), "r"(a[1]), "r"(a[2]), "r"(a[3]), "r"(b0), "r"(b1));
}

__global__ __launch_bounds__(NTHREADS, 2)
void cost_volume_mma_kernel(const float* __restrict__ ref,
                            const float* __restrict__ aux,
                            float* __restrict__ out) {
    extern __shared__ char smem[];
    const uint32_t sb = smem_u32(smem);
    const int tid  = threadIdx.x;
    const int lane = tid & 31;
    const int wid  = tid >> 5;
    const int bh    = blockIdx.y;
    const int wbase = blockIdx.x * WTILE;

    const float* refg = ref + ((size_t)bh * kRW + wbase) * kC;
    const float* auxg = aux + ((size_t)bh * kW  + wbase) * kC;

    const int mq = wid >> 1;              // m-block 0..3 -> rows 32*mq
    const int nh = wid & 1;               // n-half of the 96-col window
    const int i0 = 32 * mq;
    const int jbase = 32 * mq + 48 * nh;  // ref-col window base for this warp

    // acc[mf][fn][4]: mf = m16 frag (rows i0+16*mf..+15), fn = n8 frag
    float acc[2][6][4];
    #pragma unroll
    for (int a = 0; a < 2; ++a)
        #pragma unroll
        for (int b = 0; b < 6; ++b)
            #pragma unroll
            for (int c = 0; c < 4; ++c)
                acc[a][b][c] = 0.0f;

    // Per-lane ldmatrix addressing (k-contiguous rows, SW128 swizzle).
    // Address of (row, k-byte ko) = (row<<7) + (ko ^ ((row&7)<<4)).
    // NOTE: ko must be XORed into the swizzled column bits, not added.
    const int a_row = i0 + (lane & 15);
    const int b_row = jbase + (lane & 15);
    const int khalf = lane >> 4;
    const unsigned a_rb = (unsigned)a_row << 7;
    const unsigned b_rb = (unsigned)b_row << 7;
    const unsigned a_sw = ((unsigned)a_row & 7) << 4;
    const unsigned b_sw = ((unsigned)b_row & 7) << 4;

    for (int chunk = 0; chunk < 2; ++chunk) {
        const int cb = chunk * 64;

        // ---- stage: LDG float4 -> bf16 hi/lo split -> swizzled STS ----
        #pragma unroll 4
        for (int it = 0; it < 20; ++it) {
            int id = tid + it * NTHREADS;   // 3072 ref + 2048 aux 8B-stores
            const float* src;
            int dsth, dstl;
            if (id < BROWS * 16) {
                int r = id >> 4, fq = id & 15;
                int rr = (r < NREF) ? r : (NREF - 1);   // pad row 191
                src = refg + (size_t)rr * kC + cb + fq * 4;
                unsigned off = ((unsigned)r << 7) | ((unsigned)fq << 3);
                unsigned sw = off ^ (((unsigned)r & 7) << 4);
                dsth = OFF_BH + sw; dstl = OFF_BL + sw;
            } else {
                int id2 = id - BROWS * 16;
                int w = id2 >> 4, fq = id2 & 15;
                src = auxg + (size_t)w * kC + cb + fq * 4;
                unsigned off = ((unsigned)w << 7) | ((unsigned)fq << 3);
                unsigned sw = off ^ (((unsigned)w & 7) << 4);
                dsth = OFF_AH + sw; dstl = OFF_AL + sw;
            }
            float4 x = *reinterpret_cast<const float4*>(src);
            __nv_bfloat162 h01 = __floats2bfloat162_rn(x.x, x.y);
            __nv_bfloat162 h23 = __floats2bfloat162_rn(x.z, x.w);
            float l0 = x.x - __bfloat162float(h01.x);
            float l1 = x.y - __bfloat162float(h01.y);
            float l2 = x.z - __bfloat162float(h23.x);
            float l3 = x.w - __bfloat162float(h23.y);
            __nv_bfloat162 q01 = __floats2bfloat162_rn(l0, l1);
            __nv_bfloat162 q23 = __floats2bfloat162_rn(l2, l3);
            *reinterpret_cast<uint2*>(smem + dsth) =
                make_uint2(reinterpret_cast<unsigned&>(h01),
                           reinterpret_cast<unsigned&>(h23));
            *reinterpret_cast<uint2*>(smem + dstl) =
                make_uint2(reinterpret_cast<unsigned&>(q01),
                           reinterpret_cast<unsigned&>(q23));
        }
        __syncthreads();

        // ---- compute: 4 k-steps of 16 channels; 3 passes per k-step ----
        #pragma unroll
        for (int ks = 0; ks < 4; ++ks) {
            const unsigned ko = (unsigned)(2 * ks + khalf) << 4;
            const unsigned a_off = a_rb + (ko ^ a_sw);
            const unsigned b_off = b_rb + (ko ^ b_sw);
            uint32_t Ah0[4], Ah1[4], Al0[4], Al1[4];
            uint32_t Bh[3][4], Bl[3][4];

            ldsm_x4(Ah0, sb + OFF_AH + a_off);
            ldsm_x4(Ah1, sb + OFF_AH + a_off + 16 * 128);
            #pragma unroll
            for (int g = 0; g < 3; ++g)
                ldsm_x4(Bh[g], sb + OFF_BH + b_off + g * (16 * 128));

            // pass hh: Ah x Bh
            #pragma unroll
            for (int fn = 0; fn < 6; ++fn) {
                uint32_t b0 = Bh[fn >> 1][fn & 1];
                uint32_t b1 = Bh[fn >> 1][(fn & 1) + 2];
                mma16816(acc[0][fn], Ah0, b0, b1);
                mma16816(acc[1][fn], Ah1, b0, b1);
            }

            // pass hl: Ah x Bl
            #pragma unroll
            for (int g = 0; g < 3; ++g)
                ldsm_x4(Bl[g], sb + OFF_BL + b_off + g * (16 * 128));
            #pragma unroll
            for (int fn = 0; fn < 6; ++fn) {
                uint32_t b0 = Bl[fn >> 1][fn & 1];
                uint32_t b1 = Bl[fn >> 1][(fn & 1) + 2];
                mma16816(acc[0][fn], Ah0, b0, b1);
                mma16816(acc[1][fn], Ah1, b0, b1);
            }

            // pass lh: Al x Bh
            ldsm_x4(Al0, sb + OFF_AL + a_off);
            ldsm_x4(Al1, sb + OFF_AL + a_off + 16 * 128);
            #pragma unroll
            for (int fn = 0; fn < 6; ++fn) {
                uint32_t b0 = Bh[fn >> 1][fn & 1];
                uint32_t b1 = Bh[fn >> 1][(fn & 1) + 2];
                mma16816(acc[0][fn], Al0, b0, b1);
                mma16816(acc[1][fn], Al1, b0, b1);
            }
        }
        __syncthreads();
    }

    // ---- epilogue: band scatter out[i, i+63-j] = C[i, j] ----
    #pragma unroll
    for (int mf = 0; mf < 2; ++mf) {
        #pragma unroll
        for (int rr = 0; rr < 2; ++rr) {
            const int rA = i0 + 16 * mf + (lane >> 2) + 8 * rr;
            float* orow = out + ((size_t)(bh * kW + wbase + rA)) * kD;
            #pragma unroll
            for (int fn = 0; fn < 6; ++fn) {
                #pragma unroll
                for (int cc = 0; cc < 2; ++cc) {
                    int j = jbase + 8 * fn + 2 * (lane & 3) + cc;
                    int d = rA + 63 - j;
                    if (d >= 0 && d < kD)
                        orow[d] = acc[mf][fn][2 * rr + cc];
                }
            }
        }
    }
}

}  // namespace

extern "C" void kernel_launch(void* const* d_in, const int* in_sizes, int n_in,
                              void* d_out, int out_size) {
    const float* ref = (const float*)d_in[0];  // [1536, 447, 128] f32
    const float* aux = (const float*)d_in[1];  // [1536, 384, 128] f32
    float* out = (float*)d_out;                // [1536, 384, 64]  f32
    (void)in_sizes; (void)n_in; (void)out_size;

    cudaFuncSetAttribute(cost_volume_mma_kernel,
                         cudaFuncAttributeMaxDynamicSharedMemorySize, SMEM_TOTAL);
    dim3 grid(kW / WTILE, 1536);  // (3, 1536)
    cost_volume_mma_kernel<<<grid, NTHREADS, SMEM_TOTAL>>>(ref, aux, out);
}